// round 2
// baseline (speedup 1.0000x reference)
#include <cuda_runtime.h>

// ---------------------------------------------------------------------------
// LocalAtten: nb=1, nloc=4096, nnei=120, NI=128, ND=32, NH=4
//
// Restructured algebra:
//   p[l,h,i]   = g1[l,:] @ M_h[:,i],          M_h = Wq_h @ Wkv_k_h^T   (precomp)
//   raw[l,h,n] = gg1[l,n,:] . p[l,h,:]
//   t = (raw/sqrt(32) + 20)*sw - 20 ;  w = softmax_n(t) * sw   (mask folded in sw)
//   C[l,h,i]   = sum_n w[l,h,n] * gg1[l,n,i]
//   out[l,:]   = Cflat[l,:] @ Wfold + bh,
//     Wfold[(h*128+i)*128+j] = sum_i' Wkv[i,(32+i')*4+h] * Wh[(h*128+i')*128+j]
// ---------------------------------------------------------------------------

#define NLOC 4096
#define NNEI 120
#define NIc 128
#define NDc 32
#define NHc 4
#define SHIFTW 20.0f
#define INV_SQRT_ND 0.17677669529663688f   // 1/sqrt(32)

// scratch (static device allocations are allowed)
__device__ float d_Mcat[NIc * NHc * NIc];     // 128 x 512
__device__ float d_Wfold[NHc * NIc * NIc];    // 512 x 128
__device__ float d_P[NLOC * NHc * NIc];       // 4096 x 512
__device__ float d_C[NLOC * NHc * NIc];       // 4096 x 512

// ---------------------------------------------------------------------------
// Kernel A (merged): blocks [0,256) -> Mcat, blocks [256,512) -> Wfold
//   Mcat[i0, h*128+i]        = sum_d  Wq[i0, d*4+h]        * Wkv[i, d*4+h]
//   Wfold[(h*128+i)*128 + j] = sum_i' Wkv[i, (32+i')*4+h]  * Wh[(h*128+i')*128 + j]
// ---------------------------------------------------------------------------
__global__ __launch_bounds__(256) void precomp(const float* __restrict__ Wq,
                                               const float* __restrict__ Wkv,
                                               const float* __restrict__ Wh) {
    int b = blockIdx.x;
    int tid = threadIdx.x;
    if (b < 256) {
        int o = b * 256 + tid;                 // 65536 outputs
        int i0 = o >> 9;
        int col = o & 511;
        int h = col >> 7;
        int i = col & 127;
        float acc = 0.f;
#pragma unroll
        for (int d = 0; d < NDc; d++)
            acc += Wq[i0 * 128 + d * 4 + h] * Wkv[i * 640 + d * 4 + h];
        d_Mcat[o] = acc;
    } else {
        int o = (b - 256) * 256 + tid;         // 65536 outputs
        int r = o >> 7;                        // h*128+i
        int j = o & 127;
        int h = r >> 7;
        int i = r & 127;
        float acc = 0.f;
#pragma unroll 8
        for (int ip = 0; ip < NIc; ip++)
            acc += Wkv[i * 640 + (32 + ip) * 4 + h] * Wh[(h * 128 + ip) * 128 + j];
        d_Wfold[o] = acc;
    }
}

// ---------------------------------------------------------------------------
// Generic 64x64-tile fp32 GEMM: C = A(MxK) @ B(KxN) (+ bias per col)
// 256 threads, each computes 4x4. M,N multiples of 64; K multiple of 32.
// ---------------------------------------------------------------------------
__global__ __launch_bounds__(256) void gemm64(const float* __restrict__ A,
                                              const float* __restrict__ B,
                                              float* __restrict__ C,
                                              const float* __restrict__ bias,
                                              int M, int N, int K) {
    __shared__ float sA[32][65];   // [k][row], padded
    __shared__ float sB[32][64];   // [k][col]

    int tid = threadIdx.x;
    int tx = tid & 15;             // 4 cols each
    int ty = tid >> 4;             // 4 rows each
    int rowBase = blockIdx.y * 64;
    int colBase = blockIdx.x * 64;

    float acc[4][4];
#pragma unroll
    for (int m = 0; m < 4; m++)
#pragma unroll
        for (int n = 0; n < 4; n++) acc[m][n] = 0.f;

    for (int k0 = 0; k0 < K; k0 += 32) {
#pragma unroll
        for (int it = 0; it < 8; it++) {
            int r = (tid >> 5) + it * 8;
            int k = tid & 31;
            sA[k][r] = A[(size_t)(rowBase + r) * K + k0 + k];
        }
#pragma unroll
        for (int it = 0; it < 8; it++) {
            int k = (tid >> 6) + it * 4;
            int c = tid & 63;
            sB[k][c] = B[(size_t)(k0 + k) * N + colBase + c];
        }
        __syncthreads();

#pragma unroll
        for (int kk = 0; kk < 32; kk++) {
            float a[4];
#pragma unroll
            for (int m = 0; m < 4; m++) a[m] = sA[kk][ty * 4 + m];
            float4 bv = reinterpret_cast<const float4*>(&sB[kk][0])[tx];
            float b[4] = {bv.x, bv.y, bv.z, bv.w};
#pragma unroll
            for (int m = 0; m < 4; m++)
#pragma unroll
                for (int n = 0; n < 4; n++) acc[m][n] += a[m] * b[n];
        }
        __syncthreads();
    }

#pragma unroll
    for (int m = 0; m < 4; m++) {
        int row = rowBase + ty * 4 + m;
#pragma unroll
        for (int n = 0; n < 4; n++) {
            int col = colBase + tx * 4 + n;
            float v = acc[m][n];
            if (bias) v += bias[col];
            C[(size_t)row * N + col] = v;
        }
    }
}

// ---------------------------------------------------------------------------
// Kernel C: fused per-loc attention core. One CTA per loc.
// gg1 tile (120x128 f32 = 61.4KB) staged in smem, read from HBM exactly once.
// ---------------------------------------------------------------------------
__global__ __launch_bounds__(256) void attn_core(const float* __restrict__ gg1,
                                                 const float* __restrict__ sw,
                                                 const float* __restrict__ P,
                                                 float* __restrict__ Cout) {
    extern __shared__ float sm[];
    float* sm_gg1 = sm;                        // 120*128 = 15360
    float* sm_p   = sm + NNEI * NIc;           // 512, layout [h][i]
    float* sm_w   = sm_p + 512;                // 4*120 raw attnw -> weights
    float* sm_sw  = sm_w + NHc * NNEI;         // 120 (+pad)

    int l = blockIdx.x;
    int tid = threadIdx.x;
    int warp = tid >> 5;
    int lane = tid & 31;

    // --- stage inputs ---
    const float4* g4 = reinterpret_cast<const float4*>(gg1 + (size_t)l * NNEI * NIc);
    float4* s4 = reinterpret_cast<float4*>(sm_gg1);
#pragma unroll
    for (int k = tid; k < NNEI * NIc / 4; k += 256) s4[k] = g4[k];
    sm_p[tid]       = P[(size_t)l * 512 + tid];
    sm_p[tid + 256] = P[(size_t)l * 512 + 256 + tid];
    if (tid < NNEI) sm_sw[tid] = sw[(size_t)l * NNEI + tid];
    __syncthreads();

    // --- attnw raw: 480 dots, warp-per-dot (conflict-free vectorized LDS) ---
    for (int idx = warp; idx < NHc * NNEI; idx += 8) {
        int h = idx / NNEI;
        int n = idx - h * NNEI;
        float4 av = reinterpret_cast<const float4*>(sm_gg1 + n * NIc)[lane];
        float4 bv = reinterpret_cast<const float4*>(sm_p + h * NIc)[lane];
        float s = av.x * bv.x + av.y * bv.y + av.z * bv.z + av.w * bv.w;
#pragma unroll
        for (int o = 16; o > 0; o >>= 1) s += __shfl_xor_sync(0xffffffffu, s, o);
        if (lane == 0) sm_w[h * NNEI + n] = s;
    }
    __syncthreads();

    // --- softmax per head (warp h handles head h) ---
    if (warp < NHc) {
        int h = warp;
        float t[4];
        float mx = -1e30f;
#pragma unroll
        for (int j = 0; j < 4; j++) {
            int n = lane + 32 * j;
            if (n < NNEI) {
                float raw = sm_w[h * NNEI + n];
                t[j] = (raw * INV_SQRT_ND + SHIFTW) * sm_sw[n] - SHIFTW;
                mx = fmaxf(mx, t[j]);
            } else {
                t[j] = -1e30f;
            }
        }
#pragma unroll
        for (int o = 16; o > 0; o >>= 1)
            mx = fmaxf(mx, __shfl_xor_sync(0xffffffffu, mx, o));
        float e[4];
        float s = 0.f;
#pragma unroll
        for (int j = 0; j < 4; j++) {
            int n = lane + 32 * j;
            if (n < NNEI) {
                e[j] = __expf(t[j] - mx);
                s += e[j];
            } else {
                e[j] = 0.f;
            }
        }
#pragma unroll
        for (int o = 16; o > 0; o >>= 1) s += __shfl_xor_sync(0xffffffffu, s, o);
        float r = 1.f / s;
#pragma unroll
        for (int j = 0; j < 4; j++) {
            int n = lane + 32 * j;
            if (n < NNEI) sm_w[h * NNEI + n] = e[j] * r * sm_sw[n];
        }
    }
    __syncthreads();

    // --- C[l,h,i]: 256 threads = 64 i-pairs x 4-head split across 2 groups.
    // Thread t: i2 = (t & 63) -> float2 over i = {2*i2, 2*i2+1},
    //           hg = t >> 6   -> head hg (0..3). One LDS.64 per (n, i-pair),
    // each element used once per head; w[hg][n] is a warp-uniform broadcast.
    int i2 = tid & 63;
    int hg = tid >> 6;                 // 0..3, uniform per pair of warps
    const float* wv = sm_w + hg * NNEI;
    const float2* gg2 = reinterpret_cast<const float2*>(sm_gg1);
    float acc0 = 0.f, acc1 = 0.f;
#pragma unroll 8
    for (int n = 0; n < NNEI; n++) {
        float2 g = gg2[n * 64 + i2];
        float wn = wv[n];
        acc0 += wn * g.x;
        acc1 += wn * g.y;
    }
    float2* c2 = reinterpret_cast<float2*>(Cout + (size_t)l * 512);
    c2[hg * 64 + i2] = make_float2(acc0, acc1);
}

// ---------------------------------------------------------------------------
// Host launcher
// ---------------------------------------------------------------------------
extern "C" void kernel_launch(void* const* d_in, const int* in_sizes, int n_in,
                              void* d_out, int out_size) {
    const float* g1  = (const float*)d_in[0];
    const float* gg1 = (const float*)d_in[1];
    // d_in[2] = nlist_mask: redundant (sw already has mask folded in) — unused
    const float* sw  = (const float*)d_in[3];
    const float* Wq  = (const float*)d_in[4];
    const float* Wkv = (const float*)d_in[5];
    const float* Wh  = (const float*)d_in[6];
    const float* bh  = (const float*)d_in[7];
    float* out = (float*)d_out;

    float *pM, *pW, *pP, *pC;
    cudaGetSymbolAddress((void**)&pM, d_Mcat);
    cudaGetSymbolAddress((void**)&pW, d_Wfold);
    cudaGetSymbolAddress((void**)&pP, d_P);
    cudaGetSymbolAddress((void**)&pC, d_C);

    const int smemC = (NNEI * NIc + 512 + NHc * NNEI + 128) * (int)sizeof(float);
    cudaFuncSetAttribute(attn_core, cudaFuncAttributeMaxDynamicSharedMemorySize, smemC);

    // A: precompute folded weight matrices (merged launch)
    precomp<<<512, 256>>>(Wq, Wkv, Wh);

    // B: P = g1 (4096x128) @ Mcat (128x512)
    gemm64<<<dim3(512 / 64, NLOC / 64), 256>>>(g1, pM, pP, nullptr, NLOC, 512, 128);

    // C: fused attention core -> C scratch
    attn_core<<<NLOC, 256, smemC>>>(gg1, sw, pP, pC);

    // D: out = C (4096x512) @ Wfold (512x128) + bh
    gemm64<<<dim3(128 / 64, NLOC / 64), 256>>>(pC, pW, out, bh, NLOC, 128, 512);
}

// round 4
// speedup vs baseline: 1.2957x; 1.2957x over previous
#include <cuda_runtime.h>

// ---------------------------------------------------------------------------
// LocalAtten: nb=1, nloc=4096, nnei=120, NI=128, ND=32, NH=4
//
// Restructured algebra:
//   p[l,h,i]   = g1[l,:] @ M_h[:,i],          M_h = Wq_h @ Wkv_k_h^T   (precomp)
//   raw[l,h,n] = gg1[l,n,:] . p[l,h,:]
//   t = (raw/sqrt(32) + 20)*sw - 20 ;  w = softmax_n(t) * sw   (mask folded in sw)
//   C[l,h,i]   = sum_n w[l,h,n] * gg1[l,n,i]
//   out[l,:]   = Cflat[l,:] @ Wfold + bh
// ---------------------------------------------------------------------------

#define NLOC 4096
#define NNEI 120
#define NIc 128
#define NDc 32
#define NHc 4
#define SHIFTW 20.0f
#define INV_SQRT_ND 0.17677669529663688f   // 1/sqrt(32)

typedef unsigned long long ull;

// ---- packed f32x2 helpers (FFMA2; bit-identical to 2x fp32 FMA) ----
__device__ __forceinline__ ull pack2(float x, float y) {
    ull r; asm("mov.b64 %0, {%1,%2};" : "=l"(r) : "f"(x), "f"(y)); return r;
}
__device__ __forceinline__ float2 unpack2(ull v) {
    float2 f; asm("mov.b64 {%0,%1}, %2;" : "=f"(f.x), "=f"(f.y) : "l"(v)); return f;
}
__device__ __forceinline__ ull ffma2(ull a, ull b, ull c) {
    ull d; asm("fma.rn.f32x2 %0, %1, %2, %3;" : "=l"(d) : "l"(a), "l"(b), "l"(c)); return d;
}
__device__ __forceinline__ ull fmul2(ull a, ull b) {
    ull d; asm("mul.rn.f32x2 %0, %1, %2;" : "=l"(d) : "l"(a), "l"(b)); return d;
}

// scratch
__device__ float d_Mcat[NIc * NHc * NIc];     // 128 x 512
__device__ float d_Wfold[NHc * NIc * NIc];    // 512 x 128
__device__ float d_P[NLOC * NHc * NIc];       // 4096 x 512
__device__ float d_C[NLOC * NHc * NIc];       // 4096 x 512

// ---------------------------------------------------------------------------
// Kernel A (merged precompute)
// ---------------------------------------------------------------------------
__global__ __launch_bounds__(256) void precomp(const float* __restrict__ Wq,
                                               const float* __restrict__ Wkv,
                                               const float* __restrict__ Wh) {
    int b = blockIdx.x;
    int tid = threadIdx.x;
    if (b < 256) {
        int o = b * 256 + tid;
        int i0 = o >> 9;
        int col = o & 511;
        int h = col >> 7;
        int i = col & 127;
        float acc = 0.f;
#pragma unroll
        for (int d = 0; d < NDc; d++)
            acc += Wq[i0 * 128 + d * 4 + h] * Wkv[i * 640 + d * 4 + h];
        d_Mcat[o] = acc;
    } else {
        int o = (b - 256) * 256 + tid;
        int r = o >> 7;
        int j = o & 127;
        int h = r >> 7;
        int i = r & 127;
        float acc = 0.f;
#pragma unroll 8
        for (int ip = 0; ip < NIc; ip++)
            acc += Wkv[i * 640 + (32 + ip) * 4 + h] * Wh[(h * 128 + ip) * 128 + j];
        d_Wfold[o] = acc;
    }
}

// ---------------------------------------------------------------------------
// 64x64-tile fp32 GEMM (f32x2 inner): used for B (grid 8x64=512)
// ---------------------------------------------------------------------------
__global__ __launch_bounds__(256) void gemm64(const float* __restrict__ A,
                                              const float* __restrict__ B,
                                              float* __restrict__ C,
                                              const float* __restrict__ bias,
                                              int M, int N, int K) {
    __shared__ float sA[32][66];   // pad 66: float2-aligned rows
    __shared__ float sB[32][64];

    int tid = threadIdx.x;
    int tx = tid & 15;             // 4 cols each
    int ty = tid >> 4;             // 4 rows each
    int rowBase = blockIdx.y * 64;
    int colBase = blockIdx.x * 64;

    ull acc[4][2];
#pragma unroll
    for (int m = 0; m < 4; m++) { acc[m][0] = 0ull; acc[m][1] = 0ull; }

    for (int k0 = 0; k0 < K; k0 += 32) {
#pragma unroll
        for (int it = 0; it < 8; it++) {
            int r = (tid >> 5) + it * 8;
            int k = tid & 31;
            sA[k][r] = A[(size_t)(rowBase + r) * K + k0 + k];
        }
#pragma unroll
        for (int it = 0; it < 8; it++) {
            int k = (tid >> 6) + it * 4;
            int c = tid & 63;
            sB[k][c] = B[(size_t)(k0 + k) * N + colBase + c];
        }
        __syncthreads();

#pragma unroll
        for (int kk = 0; kk < 32; kk++) {
            float2 a01 = *reinterpret_cast<const float2*>(&sA[kk][ty * 4]);
            float2 a23 = *reinterpret_cast<const float2*>(&sA[kk][ty * 4 + 2]);
            ulonglong2 bb = reinterpret_cast<const ulonglong2*>(&sB[kk][0])[tx];
            ull d0 = pack2(a01.x, a01.x);
            ull d1 = pack2(a01.y, a01.y);
            ull d2 = pack2(a23.x, a23.x);
            ull d3 = pack2(a23.y, a23.y);
            acc[0][0] = ffma2(d0, bb.x, acc[0][0]); acc[0][1] = ffma2(d0, bb.y, acc[0][1]);
            acc[1][0] = ffma2(d1, bb.x, acc[1][0]); acc[1][1] = ffma2(d1, bb.y, acc[1][1]);
            acc[2][0] = ffma2(d2, bb.x, acc[2][0]); acc[2][1] = ffma2(d2, bb.y, acc[2][1]);
            acc[3][0] = ffma2(d3, bb.x, acc[3][0]); acc[3][1] = ffma2(d3, bb.y, acc[3][1]);
        }
        __syncthreads();
    }

#pragma unroll
    for (int m = 0; m < 4; m++) {
        int row = rowBase + ty * 4 + m;
        int col = colBase + tx * 4;
        float2 c0 = unpack2(acc[m][0]);
        float2 c1 = unpack2(acc[m][1]);
        float4 v = make_float4(c0.x, c0.y, c1.x, c1.y);
        if (bias) {
            v.x += bias[col]; v.y += bias[col + 1];
            v.z += bias[col + 2]; v.w += bias[col + 3];
        }
        *reinterpret_cast<float4*>(&C[(size_t)row * N + col]) = v;
    }
}

// ---------------------------------------------------------------------------
// 32x64-tile fp32 GEMM (f32x2 inner): used for D (grid 2x128=256)
// ---------------------------------------------------------------------------
__global__ __launch_bounds__(256) void gemm32(const float* __restrict__ A,
                                              const float* __restrict__ B,
                                              float* __restrict__ C,
                                              const float* __restrict__ bias,
                                              int M, int N, int K) {
    __shared__ float sA[32][34];   // float2-aligned rows
    __shared__ float sB[32][64];

    int tid = threadIdx.x;
    int tx = tid & 15;             // 4 cols each
    int ty = tid >> 4;             // 2 rows each
    int rowBase = blockIdx.y * 32;
    int colBase = blockIdx.x * 64;

    ull acc[2][2];
    acc[0][0] = acc[0][1] = acc[1][0] = acc[1][1] = 0ull;

    for (int k0 = 0; k0 < K; k0 += 32) {
#pragma unroll
        for (int it = 0; it < 4; it++) {
            int r = (tid >> 5) + it * 8;
            int k = tid & 31;
            sA[k][r] = A[(size_t)(rowBase + r) * K + k0 + k];
        }
#pragma unroll
        for (int it = 0; it < 8; it++) {
            int k = (tid >> 6) + it * 4;
            int c = tid & 63;
            sB[k][c] = B[(size_t)(k0 + k) * N + colBase + c];
        }
        __syncthreads();

#pragma unroll
        for (int kk = 0; kk < 32; kk++) {
            float2 a = *reinterpret_cast<const float2*>(&sA[kk][ty * 2]);
            ulonglong2 bb = reinterpret_cast<const ulonglong2*>(&sB[kk][0])[tx];
            ull d0 = pack2(a.x, a.x);
            ull d1 = pack2(a.y, a.y);
            acc[0][0] = ffma2(d0, bb.x, acc[0][0]); acc[0][1] = ffma2(d0, bb.y, acc[0][1]);
            acc[1][0] = ffma2(d1, bb.x, acc[1][0]); acc[1][1] = ffma2(d1, bb.y, acc[1][1]);
        }
        __syncthreads();
    }

#pragma unroll
    for (int m = 0; m < 2; m++) {
        int row = rowBase + ty * 2 + m;
        int col = colBase + tx * 4;
        float2 c0 = unpack2(acc[m][0]);
        float2 c1 = unpack2(acc[m][1]);
        float4 v = make_float4(c0.x, c0.y, c1.x, c1.y);
        if (bias) {
            v.x += bias[col]; v.y += bias[col + 1];
            v.z += bias[col + 2]; v.w += bias[col + 3];
        }
        *reinterpret_cast<float4*>(&C[(size_t)row * N + col]) = v;
    }
}

// ---------------------------------------------------------------------------
// Kernel C: fused per-loc attention core. One CTA per loc; gg1 tile staged in
// smem and read from smem EXACTLY ONCE per phase (p in registers, wT packed).
// smem floats: gg1 15360 | p 512 | w 512 | wT 512 | sw 128 | part 2048 = 19072
// ---------------------------------------------------------------------------
#define SM_P    15360
#define SM_W    15872
#define SM_WT   16384
#define SM_SW   16896
#define SM_PART 17024
#define SM_TOT  19072

__global__ __launch_bounds__(256, 3) void attn_core(const float* __restrict__ gg1,
                                                    const float* __restrict__ sw,
                                                    const float* __restrict__ P,
                                                    float* __restrict__ Cout) {
    extern __shared__ float sm[];
    float* sm_gg1 = sm;
    float* sm_p   = sm + SM_P;     // [h][i], h-major
    float* sm_w   = sm + SM_W;     // raw scores [h*128+n]
    float* sm_wT  = sm + SM_WT;    // final weights [n*4+h]
    float* sm_sw  = sm + SM_SW;
    float* sm_part= sm + SM_PART;  // [q][h*128+i]

    int l = blockIdx.x;
    int tid = threadIdx.x;
    int warp = tid >> 5;
    int lane = tid & 31;

    // --- stage ---
    const float4* g4 = reinterpret_cast<const float4*>(gg1 + (size_t)l * NNEI * NIc);
    float4* s4 = reinterpret_cast<float4*>(sm_gg1);
#pragma unroll
    for (int k = tid; k < NNEI * NIc / 4; k += 256) s4[k] = g4[k];
    sm_p[tid]       = P[(size_t)l * 512 + tid];
    sm_p[tid + 256] = P[(size_t)l * 512 + 256 + tid];
    if (tid < NNEI) sm_sw[tid] = sw[(size_t)l * NNEI + tid];
    __syncthreads();

    // --- phase 2: raw scores, all 4 heads per gg1 read; p in registers ---
    {
        ulonglong2 pr[NHc];
#pragma unroll
        for (int h = 0; h < NHc; h++)
            pr[h] = reinterpret_cast<const ulonglong2*>(sm_p + h * NIc)[lane];

        for (int n = warp; n < NNEI; n += 8) {
            ulonglong2 av = reinterpret_cast<const ulonglong2*>(sm_gg1 + n * NIc)[lane];
            float s[NHc];
#pragma unroll
            for (int h = 0; h < NHc; h++) {
                ull t = fmul2(av.x, pr[h].x);
                t = ffma2(av.y, pr[h].y, t);
                float2 f = unpack2(t);
                s[h] = f.x + f.y;
            }
#pragma unroll
            for (int o = 16; o > 0; o >>= 1) {
#pragma unroll
                for (int h = 0; h < NHc; h++)
                    s[h] += __shfl_xor_sync(0xffffffffu, s[h], o);
            }
            if (lane == 0) {
#pragma unroll
                for (int h = 0; h < NHc; h++) sm_w[h * 128 + n] = s[h];
            }
        }
    }
    __syncthreads();

    // --- softmax per head (warp h), writes packed wT[n*4+h] ---
    if (warp < NHc) {
        int h = warp;
        float t[4];
        float mx = -1e30f;
#pragma unroll
        for (int j = 0; j < 4; j++) {
            int n = lane + 32 * j;
            if (n < NNEI) {
                float raw = sm_w[h * 128 + n];
                t[j] = (raw * INV_SQRT_ND + SHIFTW) * sm_sw[n] - SHIFTW;
                mx = fmaxf(mx, t[j]);
            } else t[j] = -1e30f;
        }
#pragma unroll
        for (int o = 16; o > 0; o >>= 1)
            mx = fmaxf(mx, __shfl_xor_sync(0xffffffffu, mx, o));
        float e[4];
        float s = 0.f;
#pragma unroll
        for (int j = 0; j < 4; j++) {
            int n = lane + 32 * j;
            if (n < NNEI) { e[j] = __expf(t[j] - mx); s += e[j]; }
            else e[j] = 0.f;
        }
#pragma unroll
        for (int o = 16; o > 0; o >>= 1) s += __shfl_xor_sync(0xffffffffu, s, o);
        float r = 1.f / s;
#pragma unroll
        for (int j = 0; j < 4; j++) {
            int n = lane + 32 * j;
            if (n < NNEI) sm_wT[n * 4 + h] = e[j] * r * sm_sw[n];
        }
    }
    __syncthreads();

    // --- phase 3: C[h][i] = sum_n w[h][n]*gg1[n][i]; n split in 4 quarters ---
    {
        int i2 = tid & 63;         // float2 column pair
        int q = tid >> 6;          // n-quarter
        const ull* gg2 = reinterpret_cast<const ull*>(sm_gg1);
        ull acc[NHc];
        acc[0] = acc[1] = acc[2] = acc[3] = 0ull;
        int n0 = q * 30;
#pragma unroll 6
        for (int n = n0; n < n0 + 30; n++) {
            ull g = gg2[n * 64 + i2];                                    // LDS.64
            float4 wv = *reinterpret_cast<const float4*>(sm_wT + n * 4); // bcast LDS.128
            acc[0] = ffma2(g, pack2(wv.x, wv.x), acc[0]);
            acc[1] = ffma2(g, pack2(wv.y, wv.y), acc[1]);
            acc[2] = ffma2(g, pack2(wv.z, wv.z), acc[2]);
            acc[3] = ffma2(g, pack2(wv.w, wv.w), acc[3]);
        }
#pragma unroll
        for (int h = 0; h < NHc; h++) {
            float2 a = unpack2(acc[h]);
            *reinterpret_cast<float2*>(sm_part + q * 512 + h * 128 + i2 * 2) = a;
        }
    }
    __syncthreads();

    // --- combine quarters, write C ---
    {
        int o = tid * 2;
        float2 s = make_float2(0.f, 0.f);
#pragma unroll
        for (int q = 0; q < 4; q++) {
            float2 pq = *reinterpret_cast<const float2*>(sm_part + q * 512 + o);
            s.x += pq.x; s.y += pq.y;
        }
        *reinterpret_cast<float2*>(Cout + (size_t)l * 512 + o) = s;
    }
}

// ---------------------------------------------------------------------------
// Host launcher
// ---------------------------------------------------------------------------
extern "C" void kernel_launch(void* const* d_in, const int* in_sizes, int n_in,
                              void* d_out, int out_size) {
    const float* g1  = (const float*)d_in[0];
    const float* gg1 = (const float*)d_in[1];
    // d_in[2] = nlist_mask: redundant (sw already has mask folded in)
    const float* sw  = (const float*)d_in[3];
    const float* Wq  = (const float*)d_in[4];
    const float* Wkv = (const float*)d_in[5];
    const float* Wh  = (const float*)d_in[6];
    const float* bh  = (const float*)d_in[7];
    float* out = (float*)d_out;

    float *pM, *pW, *pP, *pC;
    cudaGetSymbolAddress((void**)&pM, d_Mcat);
    cudaGetSymbolAddress((void**)&pW, d_Wfold);
    cudaGetSymbolAddress((void**)&pP, d_P);
    cudaGetSymbolAddress((void**)&pC, d_C);

    const int smemC = SM_TOT * (int)sizeof(float);
    cudaFuncSetAttribute(attn_core, cudaFuncAttributeMaxDynamicSharedMemorySize, smemC);

    // A: precompute folded weight matrices
    precomp<<<512, 256>>>(Wq, Wkv, Wh);

    // B: P = g1 (4096x128) @ Mcat (128x512)
    gemm64<<<dim3(512 / 64, NLOC / 64), 256>>>(g1, pM, pP, nullptr, NLOC, 512, 128);

    // C: fused attention core -> C scratch
    attn_core<<<NLOC, 256, smemC>>>(gg1, sw, pP, pC);

    // D: out = C (4096x512) @ Wfold (512x128) + bh
    gemm32<<<dim3(128 / 64, NLOC / 32), 256>>>(pC, pW, out, bh, NLOC, 128, 512);
}

// round 5
// speedup vs baseline: 1.5351x; 1.1847x over previous
#include <cuda_runtime.h>
#include <cstdint>

// ---------------------------------------------------------------------------
// LocalAtten: nb=1, nloc=4096, nnei=120, NI=128, ND=32, NH=4
//
//   p[l,h,i]   = g1[l,:] @ M_h[:,i],          M_h = Wq_h @ Wkv_k_h^T   (precomp)
//   raw[l,h,n] = gg1[l,n,:] . p[l,h,:]
//   t = (raw/sqrt(32) + 20)*sw - 20 ;  w = softmax_n(t) * sw   (mask folded in sw)
//   C[l,h,i]   = sum_n w[l,h,n] * gg1[l,n,i]
//   out[l,:]   = Cflat[l,:] @ Wfold + bh
// ---------------------------------------------------------------------------

#define NLOC 4096
#define NNEI 120
#define NIc 128
#define NDc 32
#define NHc 4
#define SHIFTW 20.0f
#define INV_SQRT_ND 0.17677669529663688f

typedef unsigned long long ull;

__device__ __forceinline__ ull pack2(float x, float y) {
    ull r; asm("mov.b64 %0, {%1,%2};" : "=l"(r) : "f"(x), "f"(y)); return r;
}
__device__ __forceinline__ float2 unpack2(ull v) {
    float2 f; asm("mov.b64 {%0,%1}, %2;" : "=f"(f.x), "=f"(f.y) : "l"(v)); return f;
}
__device__ __forceinline__ ull ffma2(ull a, ull b, ull c) {
    ull d; asm("fma.rn.f32x2 %0, %1, %2, %3;" : "=l"(d) : "l"(a), "l"(b), "l"(c)); return d;
}
__device__ __forceinline__ ull fmul2(ull a, ull b) {
    ull d; asm("mul.rn.f32x2 %0, %1, %2;" : "=l"(d) : "l"(a), "l"(b)); return d;
}
__device__ __forceinline__ void cp_async16(uint32_t s, const void* g) {
    asm volatile("cp.async.cg.shared.global [%0], [%1], 16;" :: "r"(s), "l"(g));
}
__device__ __forceinline__ void cp_async_wait_all() {
    asm volatile("cp.async.commit_group;\ncp.async.wait_group 0;" ::: "memory");
}

// scratch
__device__ float d_Mcat[NIc * NHc * NIc];     // 128 x 512
__device__ float d_Wfold[NHc * NIc * NIc];    // 512 x 128
__device__ float d_P[NLOC * NHc * NIc];       // 4096 x 512
__device__ float d_C[NLOC * NHc * NIc];       // 4096 x 512
__device__ float d_part[2 * NLOC * NIc];      // split-K partials for D

// ---------------------------------------------------------------------------
// Kernel A (merged precompute)
// ---------------------------------------------------------------------------
__global__ __launch_bounds__(256) void precomp(const float* __restrict__ Wq,
                                               const float* __restrict__ Wkv,
                                               const float* __restrict__ Wh) {
    int b = blockIdx.x;
    int tid = threadIdx.x;
    if (b < 256) {
        int o = b * 256 + tid;
        int i0 = o >> 9;
        int col = o & 511;
        int h = col >> 7;
        int i = col & 127;
        float acc = 0.f;
#pragma unroll
        for (int d = 0; d < NDc; d++)
            acc += Wq[i0 * 128 + d * 4 + h] * Wkv[i * 640 + d * 4 + h];
        d_Mcat[o] = acc;
    } else {
        int o = (b - 256) * 256 + tid;
        int r = o >> 7;
        int j = o & 127;
        int h = r >> 7;
        int i = r & 127;
        float acc = 0.f;
#pragma unroll 8
        for (int ip = 0; ip < NIc; ip++)
            acc += Wkv[i * 640 + (32 + ip) * 4 + h] * Wh[(h * 128 + ip) * 128 + j];
        d_Wfold[o] = acc;
    }
}

// ---------------------------------------------------------------------------
// 64x64-tile GEMM for B. A values stored DUPLICATED (v,v) so the inner loop
// has zero register-duplication MOVs: 4 LDS.64 + 2 LDS.128 + 8 FFMA2 per kk.
// ---------------------------------------------------------------------------
__global__ __launch_bounds__(256) void gemm64(const float* __restrict__ A,
                                              const float* __restrict__ B,
                                              float* __restrict__ C,
                                              int M, int N, int K) {
    __shared__ float sAd[32][130];   // dup pairs: [k][2r],[2r+1]; 520B rows (8B-mult)
    __shared__ float sB[32][64];

    int tid = threadIdx.x;
    int tx = tid & 15;
    int ty = tid >> 4;
    int rowBase = blockIdx.y * 64;
    int colBase = blockIdx.x * 64;

    ull acc[4][2];
#pragma unroll
    for (int m = 0; m < 4; m++) { acc[m][0] = 0ull; acc[m][1] = 0ull; }

    for (int k0 = 0; k0 < K; k0 += 32) {
#pragma unroll
        for (int it = 0; it < 8; it++) {
            int r = (tid >> 5) + it * 8;
            int k = tid & 31;
            float v = A[(size_t)(rowBase + r) * K + k0 + k];
            *reinterpret_cast<ull*>(&sAd[k][2 * r]) = pack2(v, v);
        }
#pragma unroll
        for (int it = 0; it < 8; it++) {
            int k = (tid >> 6) + it * 4;
            int c = tid & 63;
            sB[k][c] = B[(size_t)(k0 + k) * N + colBase + c];
        }
        __syncthreads();

#pragma unroll
        for (int kk = 0; kk < 32; kk++) {
            ull a0 = *reinterpret_cast<const ull*>(&sAd[kk][ty * 8]);
            ull a1 = *reinterpret_cast<const ull*>(&sAd[kk][ty * 8 + 2]);
            ull a2 = *reinterpret_cast<const ull*>(&sAd[kk][ty * 8 + 4]);
            ull a3 = *reinterpret_cast<const ull*>(&sAd[kk][ty * 8 + 6]);
            ulonglong2 bb = reinterpret_cast<const ulonglong2*>(&sB[kk][0])[tx];
            acc[0][0] = ffma2(a0, bb.x, acc[0][0]); acc[0][1] = ffma2(a0, bb.y, acc[0][1]);
            acc[1][0] = ffma2(a1, bb.x, acc[1][0]); acc[1][1] = ffma2(a1, bb.y, acc[1][1]);
            acc[2][0] = ffma2(a2, bb.x, acc[2][0]); acc[2][1] = ffma2(a2, bb.y, acc[2][1]);
            acc[3][0] = ffma2(a3, bb.x, acc[3][0]); acc[3][1] = ffma2(a3, bb.y, acc[3][1]);
        }
        __syncthreads();
    }

#pragma unroll
    for (int m = 0; m < 4; m++) {
        int row = rowBase + ty * 4 + m;
        int col = colBase + tx * 4;
        float2 c0 = unpack2(acc[m][0]);
        float2 c1 = unpack2(acc[m][1]);
        float4 v = make_float4(c0.x, c0.y, c1.x, c1.y);
        *reinterpret_cast<float4*>(&C[(size_t)row * N + col]) = v;
    }
}

// ---------------------------------------------------------------------------
// 32x64-tile split-K GEMM for D: grid (N/64, M/32, 2). Each z computes a
// K/2 chunk into d_part[z]. Dup-A storage; 2 LDS.64 + 1 LDS.128 + 4 FFMA2/kk.
// ---------------------------------------------------------------------------
__global__ __launch_bounds__(256) void gemm32k(const float* __restrict__ A,
                                               const float* __restrict__ B,
                                               float* __restrict__ Part,
                                               int M, int N, int K) {
    __shared__ float sAd[32][66];   // dup pairs; 264B rows
    __shared__ float sB[32][64];

    int tid = threadIdx.x;
    int tx = tid & 15;
    int ty = tid >> 4;
    int rowBase = blockIdx.y * 32;
    int colBase = blockIdx.x * 64;
    int kHalf = K >> 1;
    int kBeg = blockIdx.z * kHalf;
    float* out = Part + (size_t)blockIdx.z * M * N;

    ull acc[2][2];
    acc[0][0] = acc[0][1] = acc[1][0] = acc[1][1] = 0ull;

    for (int k0 = 0; k0 < kHalf; k0 += 32) {
#pragma unroll
        for (int it = 0; it < 4; it++) {
            int r = (tid >> 5) + it * 8;
            int k = tid & 31;
            float v = A[(size_t)(rowBase + r) * K + kBeg + k0 + k];
            *reinterpret_cast<ull*>(&sAd[k][2 * r]) = pack2(v, v);
        }
#pragma unroll
        for (int it = 0; it < 8; it++) {
            int k = (tid >> 6) + it * 4;
            int c = tid & 63;
            sB[k][c] = B[(size_t)(kBeg + k0 + k) * N + colBase + c];
        }
        __syncthreads();

#pragma unroll
        for (int kk = 0; kk < 32; kk++) {
            ull a0 = *reinterpret_cast<const ull*>(&sAd[kk][ty * 4]);
            ull a1 = *reinterpret_cast<const ull*>(&sAd[kk][ty * 4 + 2]);
            ulonglong2 bb = reinterpret_cast<const ulonglong2*>(&sB[kk][0])[tx];
            acc[0][0] = ffma2(a0, bb.x, acc[0][0]); acc[0][1] = ffma2(a0, bb.y, acc[0][1]);
            acc[1][0] = ffma2(a1, bb.x, acc[1][0]); acc[1][1] = ffma2(a1, bb.y, acc[1][1]);
        }
        __syncthreads();
    }

#pragma unroll
    for (int m = 0; m < 2; m++) {
        int row = rowBase + ty * 2 + m;
        int col = colBase + tx * 4;
        float2 c0 = unpack2(acc[m][0]);
        float2 c1 = unpack2(acc[m][1]);
        float4 v = make_float4(c0.x, c0.y, c1.x, c1.y);
        *reinterpret_cast<float4*>(&out[(size_t)row * N + col]) = v;
    }
}

// Combine split-K partials + bias.  4096*128 floats = 131072 float4.
__global__ __launch_bounds__(256) void reduce_bias(const float* __restrict__ Part,
                                                   const float* __restrict__ bias,
                                                   float* __restrict__ out) {
    int idx = blockIdx.x * 256 + threadIdx.x;
    float4 a = reinterpret_cast<const float4*>(Part)[idx];
    float4 b = reinterpret_cast<const float4*>(Part + NLOC * NIc)[idx];
    float4 bi = reinterpret_cast<const float4*>(bias)[idx & 31];
    float4 v = make_float4(a.x + b.x + bi.x, a.y + b.y + bi.y,
                           a.z + b.z + bi.z, a.w + b.w + bi.w);
    reinterpret_cast<float4*>(out)[idx] = v;
}

// ---------------------------------------------------------------------------
// Kernel C: fused per-loc attention core. One CTA per loc.
// smem (floats): gg1 15360 | p 512 | wT2(dup ull) 960 | sw 128 | w/part 2048
// total 19008 floats = 76032 B -> 3 CTAs/SM.
// ---------------------------------------------------------------------------
#define SM_P    15360
#define SM_WT2  15872
#define SM_SW   16832
#define SM_WPART 16960
#define SM_TOT  19008

__global__ __launch_bounds__(256, 3) void attn_core(const float* __restrict__ gg1,
                                                    const float* __restrict__ sw,
                                                    const float* __restrict__ P,
                                                    float* __restrict__ Cout) {
    extern __shared__ float sm[];
    float* sm_gg1 = sm;
    float* sm_p   = sm + SM_P;                         // [h][i]
    ull*   sm_wT2 = reinterpret_cast<ull*>(sm + SM_WT2); // [n*4+h] dup pairs
    float* sm_sw  = sm + SM_SW;
    float* sm_w   = sm + SM_WPART;                     // raw scores [h*128+n]
    float* sm_part= sm + SM_WPART;                     // reused after softmax

    int l = blockIdx.x;
    int tid = threadIdx.x;
    int warp = tid >> 5;
    int lane = tid & 31;

    // --- stage gg1 via cp.async; p/sw via normal loads ---
    {
        const float4* g4 = reinterpret_cast<const float4*>(gg1 + (size_t)l * NNEI * NIc);
        uint32_t sbase = (uint32_t)__cvta_generic_to_shared(sm_gg1);
#pragma unroll
        for (int k = tid; k < NNEI * NIc / 4; k += 256)
            cp_async16(sbase + k * 16, g4 + k);
        sm_p[tid]       = P[(size_t)l * 512 + tid];
        sm_p[tid + 256] = P[(size_t)l * 512 + 256 + tid];
        if (tid < NNEI) sm_sw[tid] = sw[(size_t)l * NNEI + tid];
        cp_async_wait_all();
    }
    __syncthreads();

    // --- phase 2: raw scores; warp-per-n, 4 heads per gg1 read, p in regs ---
    {
        ulonglong2 pr[NHc];
#pragma unroll
        for (int h = 0; h < NHc; h++)
            pr[h] = reinterpret_cast<const ulonglong2*>(sm_p + h * NIc)[lane];

        for (int n = warp; n < NNEI; n += 8) {
            ulonglong2 av = reinterpret_cast<const ulonglong2*>(sm_gg1 + n * NIc)[lane];
            float s0, s1, s2, s3;
            {
                ull t0 = fmul2(av.x, pr[0].x); t0 = ffma2(av.y, pr[0].y, t0);
                ull t1 = fmul2(av.x, pr[1].x); t1 = ffma2(av.y, pr[1].y, t1);
                ull t2 = fmul2(av.x, pr[2].x); t2 = ffma2(av.y, pr[2].y, t2);
                ull t3 = fmul2(av.x, pr[3].x); t3 = ffma2(av.y, pr[3].y, t3);
                float2 f0 = unpack2(t0), f1 = unpack2(t1), f2 = unpack2(t2), f3 = unpack2(t3);
                s0 = f0.x + f0.y; s1 = f1.x + f1.y; s2 = f2.x + f2.y; s3 = f3.x + f3.y;
            }
            // rounds 16,8,4: each lane -> partial over its mod-4 lane class
#pragma unroll
            for (int o = 16; o >= 4; o >>= 1) {
                s0 += __shfl_xor_sync(0xffffffffu, s0, o);
                s1 += __shfl_xor_sync(0xffffffffu, s1, o);
                s2 += __shfl_xor_sync(0xffffffffu, s2, o);
                s3 += __shfl_xor_sync(0xffffffffu, s3, o);
            }
            // lane group-of-8 picks its head; rounds 2,1 combine the 4 classes
            float v = (lane & 16) ? ((lane & 8) ? s3 : s2)
                                  : ((lane & 8) ? s1 : s0);
            v += __shfl_xor_sync(0xffffffffu, v, 2);
            v += __shfl_xor_sync(0xffffffffu, v, 1);
            if ((lane & 7) == 0) sm_w[(lane >> 3) * 128 + n] = v;
        }
    }
    __syncthreads();

    // --- softmax per head (warp h); writes DUPLICATED pairs wT2[n*4+h] ---
    if (warp < NHc) {
        int h = warp;
        float t[4];
        float mx = -1e30f;
#pragma unroll
        for (int j = 0; j < 4; j++) {
            int n = lane + 32 * j;
            if (n < NNEI) {
                float raw = sm_w[h * 128 + n];
                t[j] = (raw * INV_SQRT_ND + SHIFTW) * sm_sw[n] - SHIFTW;
                mx = fmaxf(mx, t[j]);
            } else t[j] = -1e30f;
        }
#pragma unroll
        for (int o = 16; o > 0; o >>= 1)
            mx = fmaxf(mx, __shfl_xor_sync(0xffffffffu, mx, o));
        float e[4];
        float s = 0.f;
#pragma unroll
        for (int j = 0; j < 4; j++) {
            int n = lane + 32 * j;
            if (n < NNEI) { e[j] = __expf(t[j] - mx); s += e[j]; }
            else e[j] = 0.f;
        }
#pragma unroll
        for (int o = 16; o > 0; o >>= 1) s += __shfl_xor_sync(0xffffffffu, s, o);
        float r = 1.f / s;
#pragma unroll
        for (int j = 0; j < 4; j++) {
            int n = lane + 32 * j;
            if (n < NNEI) {
                float w = e[j] * r * sm_sw[n];
                sm_wT2[n * 4 + h] = pack2(w, w);
            }
        }
    }
    __syncthreads();

    // --- phase 3: C[h][i] = sum_n w[h][n]*gg1[n][i]; n in 4 quarters ---
    {
        int i2 = tid & 63;
        int q = tid >> 6;
        const ull* gg2 = reinterpret_cast<const ull*>(sm_gg1);
        ull acc0 = 0, acc1 = 0, acc2 = 0, acc3 = 0;
        int n0 = q * 30;
#pragma unroll 6
        for (int n = n0; n < n0 + 30; n++) {
            ull g = gg2[n * 64 + i2];                                          // LDS.64
            ulonglong2 w01 = *reinterpret_cast<const ulonglong2*>(&sm_wT2[n * 4]);     // bcast
            ulonglong2 w23 = *reinterpret_cast<const ulonglong2*>(&sm_wT2[n * 4 + 2]); // bcast
            acc0 = ffma2(g, w01.x, acc0);
            acc1 = ffma2(g, w01.y, acc1);
            acc2 = ffma2(g, w23.x, acc2);
            acc3 = ffma2(g, w23.y, acc3);
        }
        float2 a0 = unpack2(acc0), a1 = unpack2(acc1), a2 = unpack2(acc2), a3 = unpack2(acc3);
        *reinterpret_cast<float2*>(sm_part + q * 512 +   0 + i2 * 2) = a0;
        *reinterpret_cast<float2*>(sm_part + q * 512 + 128 + i2 * 2) = a1;
        *reinterpret_cast<float2*>(sm_part + q * 512 + 256 + i2 * 2) = a2;
        *reinterpret_cast<float2*>(sm_part + q * 512 + 384 + i2 * 2) = a3;
    }
    __syncthreads();

    // --- combine quarters, write C ---
    {
        int o = tid * 2;
        float2 s = make_float2(0.f, 0.f);
#pragma unroll
        for (int q = 0; q < 4; q++) {
            float2 pq = *reinterpret_cast<const float2*>(sm_part + q * 512 + o);
            s.x += pq.x; s.y += pq.y;
        }
        *reinterpret_cast<float2*>(Cout + (size_t)l * 512 + o) = s;
    }
}

// ---------------------------------------------------------------------------
// Host launcher
// ---------------------------------------------------------------------------
extern "C" void kernel_launch(void* const* d_in, const int* in_sizes, int n_in,
                              void* d_out, int out_size) {
    const float* g1  = (const float*)d_in[0];
    const float* gg1 = (const float*)d_in[1];
    // d_in[2] = nlist_mask: redundant (sw already has mask folded in)
    const float* sw  = (const float*)d_in[3];
    const float* Wq  = (const float*)d_in[4];
    const float* Wkv = (const float*)d_in[5];
    const float* Wh  = (const float*)d_in[6];
    const float* bh  = (const float*)d_in[7];
    float* out = (float*)d_out;

    float *pM, *pW, *pP, *pC, *pPart;
    cudaGetSymbolAddress((void**)&pM, d_Mcat);
    cudaGetSymbolAddress((void**)&pW, d_Wfold);
    cudaGetSymbolAddress((void**)&pP, d_P);
    cudaGetSymbolAddress((void**)&pC, d_C);
    cudaGetSymbolAddress((void**)&pPart, d_part);

    const int smemC = SM_TOT * (int)sizeof(float);
    cudaFuncSetAttribute(attn_core, cudaFuncAttributeMaxDynamicSharedMemorySize, smemC);

    // A: precompute folded weight matrices
    precomp<<<512, 256>>>(Wq, Wkv, Wh);

    // B: P = g1 (4096x128) @ Mcat (128x512)
    gemm64<<<dim3(512 / 64, NLOC / 64), 256>>>(g1, pM, pP, NLOC, 512, 128);

    // C: fused attention core -> C scratch
    attn_core<<<NLOC, 256, smemC>>>(gg1, sw, pP, pC);

    // D: out = C (4096x512) @ Wfold (512x128) + bh   (split-K=2 + reduce)
    gemm32k<<<dim3(128 / 64, NLOC / 32, 2), 256>>>(pC, pW, pPart, NLOC, 128, 512);
    reduce_bias<<<512, 256>>>(pPart, bh, out);
}